// round 13
// baseline (speedup 1.0000x reference)
#include <cuda_runtime.h>
#include <math.h>

#define NN 50000
#define EE 800000
#define LLAYERS 3
#define DD 64
#define GG 512
#define GDIM 128

// ---------------- scratch (static __device__, no allocs) ----------------
__device__ int   g_deg[NN];
__device__ int   g_fill[NN];
__device__ int   g_rowptr[NN + 1];
__device__ int2  g_edge[EE];          // packed {src, __float_as_int(ea)}
__device__ float g_Q[NN * DD];
__device__ float g_KV[NN * 2 * DD];   // per node: [0:64)=K, [64:128)=V (one 512B row)
__device__ float g_S[NN * DD];        // skip = x @ Wskip + bskip
__device__ float g_h[NN * DD];        // layer output (ReLU already applied for l<L-1)
__device__ float g_pool[GG * DD];
__device__ int   g_cnt[GG];

// ---------------- packed fp32x2 FMA (sm_100+) ----------------
__device__ __forceinline__ float2 ffma2(float2 x, float2 w, float2 a) {
    float2 r;
    asm("fma.rn.f32x2 %0, %1, %2, %3;"
        : "=l"(reinterpret_cast<unsigned long long&>(r))
        : "l"(reinterpret_cast<unsigned long long&>(x)),
          "l"(reinterpret_cast<unsigned long long&>(w)),
          "l"(reinterpret_cast<unsigned long long&>(a)));
    return r;
}

// ---------------- utility ----------------
__global__ void zero_scratch_kernel() {
    int idx = blockIdx.x * blockDim.x + threadIdx.x;
    int stride = gridDim.x * blockDim.x;
    for (int i = idx; i < NN; i += stride) { g_deg[i] = 0; g_fill[i] = 0; }
    for (int i = idx; i < GG * DD; i += stride) g_pool[i] = 0.f;
    for (int i = idx; i < GG; i += stride) g_cnt[i] = 0;
}

// 4 edges per thread via int4 loads (EE % 4 == 0)
__global__ void hist_kernel(const int* __restrict__ dst) {
    int t = blockIdx.x * blockDim.x + threadIdx.x;
    int e = t * 4;
    if (e + 3 < EE) {
        int4 d4 = *reinterpret_cast<const int4*>(dst + e);
        atomicAdd(&g_deg[d4.x], 1);
        atomicAdd(&g_deg[d4.y], 1);
        atomicAdd(&g_deg[d4.z], 1);
        atomicAdd(&g_deg[d4.w], 1);
    } else {
        for (int i = e; i < EE; i++) atomicAdd(&g_deg[dst[i]], 1);
    }
}

// raking scan: 1024 threads, each owns 49 consecutive elements.
__global__ void scan_kernel() {
    __shared__ int sh[1024];
    int t = threadIdx.x;
    const int PER = (NN + 1023) / 1024;  // 49
    int base = t * PER;
    int sum = 0;
#pragma unroll 7
    for (int i = 0; i < PER; i++) {
        int idx = base + i;
        if (idx < NN) sum += g_deg[idx];
    }
    sh[t] = sum;
    __syncthreads();
    for (int off = 1; off < 1024; off <<= 1) {
        int v = (t >= off) ? sh[t - off] : 0;
        __syncthreads();
        sh[t] += v;
        __syncthreads();
    }
    int run = sh[t] - sum;  // exclusive prefix
    for (int i = 0; i < PER; i++) {
        int idx = base + i;
        if (idx < NN) {
            g_rowptr[idx] = run;
            run += g_deg[idx];
        }
    }
    if (t == 1023) g_rowptr[NN] = sh[1023];
}

__global__ void scatter_kernel(const int* __restrict__ src, const int* __restrict__ dst,
                               const float* __restrict__ ea) {
    int e = blockIdx.x * blockDim.x + threadIdx.x;
    if (e >= EE) return;
    int d = dst[e];
    int pos = g_rowptr[d] + atomicAdd(&g_fill[d], 1);
    g_edge[pos] = make_int2(src[e], __float_as_int(ea[e]));
}

// ---------------- fused QKV+Skip projection, FFMA2, TN=32, PERSISTENT W ----------
// 296 blocks (2/SM); each loads W once into smem and loops over ~5-6 node tiles.
// Cuts W L2 traffic 100MB -> 19MB per layer. Inner mainloop identical to the
// proven TN=32 config.
#define TN 32
#define GEMM_GRID 296
__global__ __launch_bounds__(256) void gemm_qkvs(
    const float* __restrict__ X, int useX,
    const float* __restrict__ Wq, const float* __restrict__ bq,
    const float* __restrict__ Wk, const float* __restrict__ bk,
    const float* __restrict__ Wv, const float* __restrict__ bv,
    const float* __restrict__ Wsk, const float* __restrict__ bsk)
{
    extern __shared__ float sh[];
    float* Wsm = sh;                 // [64][256]
    float* Xsm = sh + 64 * 256;      // [TN][64]
    int tid = threadIdx.x;

    // Load W once (float4: 4 values per load). 64*64 floats per matrix.
    for (int i = tid * 4; i < 64 * 64; i += 256 * 4) {
        int d = i >> 6, j = i & 63;
        float4 vq = *reinterpret_cast<const float4*>(Wq + i);
        float4 vk = *reinterpret_cast<const float4*>(Wk + i);
        float4 vv = *reinterpret_cast<const float4*>(Wv + i);
        float4 vs = *reinterpret_cast<const float4*>(Wsk + i);
        *reinterpret_cast<float4*>(&Wsm[d * 256 + j])       = vq;
        *reinterpret_cast<float4*>(&Wsm[d * 256 + 64 + j])  = vk;
        *reinterpret_cast<float4*>(&Wsm[d * 256 + 128 + j]) = vv;
        *reinterpret_cast<float4*>(&Wsm[d * 256 + 192 + j]) = vs;
    }

    int cg = tid & 31;   // col pair base = 2*cg
    int ng = tid >> 5;   // nodes ng*4 + n
    int colp = 2 * cg;
    float2 bQ, bK, bV, bS;
    bQ = make_float2(bq[colp],  bq[colp + 1]);
    bK = make_float2(bk[colp],  bk[colp + 1]);
    bV = make_float2(bv[colp],  bv[colp + 1]);
    bS = make_float2(bsk[colp], bsk[colp + 1]);

    const int numTiles = (NN + TN - 1) / TN;
    for (int tile = blockIdx.x; tile < numTiles; tile += GEMM_GRID) {
        int nodeBase = tile * TN;
        __syncthreads();   // Xsm of previous tile fully consumed; also orders Wsm store
        for (int i = tid; i < TN * 64; i += 256) {
            int n = i >> 6, d = i & 63;
            int gn = nodeBase + n;
            float v = 0.f;
            if (gn < NN) v = useX ? X[gn * 64 + d] : g_h[gn * 64 + d];
            Xsm[n * 64 + d] = v;
        }
        __syncthreads();

        float2 acc[4][4];
#pragma unroll
        for (int n = 0; n < 4; n++)
#pragma unroll
            for (int c = 0; c < 4; c++) acc[n][c] = make_float2(0.f, 0.f);

#pragma unroll 4
        for (int d = 0; d < 64; d++) {
            float2 w[4];
#pragma unroll
            for (int c = 0; c < 4; c++)
                w[c] = *reinterpret_cast<const float2*>(&Wsm[d * 256 + 2 * cg + 64 * c]);
#pragma unroll
            for (int n = 0; n < 4; n++) {
                float xv = Xsm[(ng * 4 + n) * 64 + d];
                float2 xx = make_float2(xv, xv);
#pragma unroll
                for (int c = 0; c < 4; c++) acc[n][c] = ffma2(xx, w[c], acc[n][c]);
            }
        }

#pragma unroll
        for (int n = 0; n < 4; n++) {
            int gn = nodeBase + ng * 4 + n;
            if (gn >= NN) continue;
            float2 rq = make_float2(acc[n][0].x + bQ.x, acc[n][0].y + bQ.y);
            float2 rk = make_float2(acc[n][1].x + bK.x, acc[n][1].y + bK.y);
            float2 rv = make_float2(acc[n][2].x + bV.x, acc[n][2].y + bV.y);
            float2 rs = make_float2(acc[n][3].x + bS.x, acc[n][3].y + bS.y);
            *reinterpret_cast<float2*>(&g_Q[gn * 64 + colp])        = rq;
            *reinterpret_cast<float2*>(&g_KV[gn * 128 + colp])      = rk;
            *reinterpret_cast<float2*>(&g_KV[gn * 128 + 64 + colp]) = rv;
            *reinterpret_cast<float2*>(&g_S[gn * 64 + colp])        = rs;
        }
    }
}

// ---------------- attention: HALF-WARP per node, float4 lanes, 64-thread blocks ----
__global__ __launch_bounds__(64) void attn_kernel(const float* __restrict__ We_l,
                                                  float* __restrict__ dout, int toDout)
{
    int gid = (blockIdx.x * blockDim.x + threadIdx.x) >> 4;   // node id
    int l16 = threadIdx.x & 15;
    if (gid >= NN) return;
    unsigned gmask = 0xFFFFu << (threadIdx.x & 16);           // this half-warp

    float4 q = reinterpret_cast<const float4*>(g_Q + (size_t)gid * 64)[l16];
    q.x *= 0.25f; q.y *= 0.25f; q.z *= 0.25f; q.w *= 0.25f;   // fold 1/sqrt(C)
    float4 we = reinterpret_cast<const float4*>(We_l)[l16];

    float lsum = 0.f;
    float4 acc = make_float4(0.f, 0.f, 0.f, 0.f);

    int beg = g_rowptr[gid], end = g_rowptr[gid + 1];
    int p = beg;

#define EDGE_BODY(K, V, EAI)                                              \
    {                                                                     \
        float ea = __int_as_float(EAI);                                   \
        float kx = fmaf(ea, we.x, (K).x);                                 \
        float ky = fmaf(ea, we.y, (K).y);                                 \
        float kz = fmaf(ea, we.z, (K).z);                                 \
        float kw = fmaf(ea, we.w, (K).w);                                 \
        float d = q.x * kx;                                               \
        d = fmaf(q.y, ky, d);                                             \
        d = fmaf(q.z, kz, d);                                             \
        d = fmaf(q.w, kw, d);                                             \
        d += __shfl_xor_sync(gmask, d, 1);                                \
        d += __shfl_xor_sync(gmask, d, 2);                                \
        float pe = __expf(d);                                             \
        acc.x = fmaf(pe, fmaf(ea, we.x, (V).x), acc.x);                   \
        acc.y = fmaf(pe, fmaf(ea, we.y, (V).y), acc.y);                   \
        acc.z = fmaf(pe, fmaf(ea, we.z, (V).z), acc.z);                   \
        acc.w = fmaf(pe, fmaf(ea, we.w, (V).w), acc.w);                   \
        lsum += pe;                                                       \
    }

    for (; p + 2 <= end; p += 2) {
        int2 ed0 = g_edge[p];
        int2 ed1 = g_edge[p + 1];
        const float4* kv0 = reinterpret_cast<const float4*>(g_KV + (size_t)ed0.x * 128);
        const float4* kv1 = reinterpret_cast<const float4*>(g_KV + (size_t)ed1.x * 128);
        float4 k0 = kv0[l16], v0 = kv0[16 + l16];
        float4 k1 = kv1[l16], v1 = kv1[16 + l16];
        EDGE_BODY(k0, v0, ed0.y)
        EDGE_BODY(k1, v1, ed1.y)
    }
    if (p < end) {
        int2 ed = g_edge[p];
        const float4* kvp = reinterpret_cast<const float4*>(g_KV + (size_t)ed.x * 128);
        float4 k = kvp[l16], v = kvp[16 + l16];
        EDGE_BODY(k, v, ed.y)
    }
#undef EDGE_BODY

    float inv = (lsum > 0.f) ? 1.f / lsum : 0.f;
    float4 s = reinterpret_cast<const float4*>(g_S + (size_t)gid * 64)[l16];
    float4 r;
    r.x = fmaf(acc.x, inv, s.x);
    r.y = fmaf(acc.y, inv, s.y);
    r.z = fmaf(acc.z, inv, s.z);
    r.w = fmaf(acc.w, inv, s.w);
    if (toDout) {
        reinterpret_cast<float4*>(dout + (size_t)gid * 64)[l16] = r;
    } else {
        r.x = fmaxf(r.x, 0.f); r.y = fmaxf(r.y, 0.f);
        r.z = fmaxf(r.z, 0.f); r.w = fmaxf(r.w, 0.f);
        reinterpret_cast<float4*>(g_h + (size_t)gid * 64)[l16] = r;
    }
}

// ---------------- pooling: batch sorted -> run-length accumulate (+count) ----------------
__global__ void pool_kernel(const float* __restrict__ h, const int* __restrict__ batch) {
    int c = threadIdx.x;           // 64 threads = channels
    int n0 = blockIdx.x * 32;
    int cur = -1;
    float acc = 0.f;
    int cnt = 0;
    for (int i = 0; i < 32; i++) {
        int n = n0 + i;
        if (n >= NN) break;
        int b = batch[n];
        if (b != cur) {
            if (cur >= 0) {
                atomicAdd(&g_pool[cur * 64 + c], acc);
                if (c == 0) atomicAdd(&g_cnt[cur], cnt);
            }
            cur = b; acc = 0.f; cnt = 0;
        }
        acc += h[n * 64 + c];
        cnt++;
    }
    if (cur >= 0) {
        atomicAdd(&g_pool[cur * 64 + c], acc);
        if (c == 0) atomicAdd(&g_cnt[cur], cnt);
    }
}

// ---------------- graph MLP head ----------------
__global__ void mlp_kernel(const float* __restrict__ W1, const float* __restrict__ b1,
                           const float* __restrict__ W2, const float* __restrict__ b2,
                           const float* __restrict__ W3, const float* __restrict__ b3,
                           float* __restrict__ out)
{
    int g = blockIdx.x;
    int t = threadIdx.x; // 128
    __shared__ float gsh[64], h1[64], h2[16];
    if (t < 64) {
        float c = fmaxf((float)g_cnt[g], 1.f);
        gsh[t] = g_pool[g * 64 + t] / c;
    }
    __syncthreads();
    if (t < 64) {
        float a = b1[t];
#pragma unroll 8
        for (int d = 0; d < 64; d++) a = fmaf(gsh[d], W1[d * 64 + t], a);
        h1[t] = fmaxf(a, 0.f);
    }
    __syncthreads();
    if (t < 16) {
        float a = b2[t];
#pragma unroll 8
        for (int d = 0; d < 64; d++) a = fmaf(h1[d], W2[d * 16 + t], a);
        h2[t] = fmaxf(a, 0.f);
    }
    __syncthreads();
    {
        float a = b3[t];
#pragma unroll
        for (int d = 0; d < 16; d++) a = fmaf(h2[d], W3[d * 128 + t], a);
        out[g * 128 + t] = a;
    }
}

// ---------------- launch (serial, proven ordering) ----------------
extern "C" void kernel_launch(void* const* d_in, const int* in_sizes, int n_in,
                              void* d_out, int out_size)
{
    // Resolve input ordering by size probe (edge_index has 2*E elements).
    const int* ei;
    const int* batch;
    int iW;
    if (in_sizes[2] == 2 * EE) {          // dict order: x, ea, edge_index, batch, Wq...
        ei    = (const int*)d_in[2];
        batch = (const int*)d_in[3];
        iW = 4;
    } else {                               // signature order: x, ea, Wq..., edge_index, batch
        ei    = (const int*)d_in[17];
        batch = (const int*)d_in[18];
        iW = 2;
    }
    const float* x    = (const float*)d_in[0];
    const float* ea   = (const float*)d_in[1];
    const float* Wq   = (const float*)d_in[iW + 0];
    const float* bq   = (const float*)d_in[iW + 1];
    const float* Wk   = (const float*)d_in[iW + 2];
    const float* bk   = (const float*)d_in[iW + 3];
    const float* Wv   = (const float*)d_in[iW + 4];
    const float* bv   = (const float*)d_in[iW + 5];
    const float* We   = (const float*)d_in[iW + 6];
    const float* Wsk  = (const float*)d_in[iW + 7];
    const float* bsk  = (const float*)d_in[iW + 8];
    const float* W1   = (const float*)d_in[iW + 9];
    const float* b1   = (const float*)d_in[iW + 10];
    const float* W2   = (const float*)d_in[iW + 11];
    const float* b2   = (const float*)d_in[iW + 12];
    const float* W3   = (const float*)d_in[iW + 13];
    const float* b3   = (const float*)d_in[iW + 14];

    const int* srcIdx = ei;
    const int* dstIdx = ei + EE;
    float* out = (float*)d_out;

    static bool attr_set = false;
    if (!attr_set) {
        cudaFuncSetAttribute(gemm_qkvs, cudaFuncAttributeMaxDynamicSharedMemorySize,
                             (64 * 256 + TN * 64) * sizeof(float));
        attr_set = true;
    }

    // CSR build (serial; reused by all 3 layers)
    zero_scratch_kernel<<<256, 256>>>();
    hist_kernel<<<(EE / 4 + 255) / 256, 256>>>(dstIdx);
    scan_kernel<<<1, 1024>>>();
    scatter_kernel<<<(EE + 255) / 256, 256>>>(srcIdx, dstIdx, ea);

    size_t smem = (64 * 256 + TN * 64) * sizeof(float);
    int attnGrid = (NN * 16 + 63) / 64;

    for (int l = 0; l < LLAYERS; l++) {
        int useX = (l == 0) ? 1 : 0;
        gemm_qkvs<<<GEMM_GRID, 256, smem>>>(
            x, useX,
            Wq + l * DD * DD, bq + l * DD,
            Wk + l * DD * DD, bk + l * DD,
            Wv + l * DD * DD, bv + l * DD,
            Wsk + l * DD * DD, bsk + l * DD);
        int toDout = (l == LLAYERS - 1) ? 1 : 0;
        attn_kernel<<<attnGrid, 64>>>(We + l * DD, out, toDout);
    }

    // pool over final node embeddings (already in d_out) + MLP head
    pool_kernel<<<(NN + 31) / 32, 64>>>(out, batch);
    mlp_kernel<<<GG, 128>>>(W1, b1, W2, b2, W3, b3, out + (size_t)NN * DD);
}

// round 14
// speedup vs baseline: 1.3679x; 1.3679x over previous
#include <cuda_runtime.h>
#include <math.h>

#define NN 50000
#define EE 800000
#define LLAYERS 3
#define DD 64
#define GG 512
#define GDIM 128

// ---------------- scratch (static __device__, no allocs) ----------------
__device__ int   g_deg[NN];
__device__ int   g_fill[NN];
__device__ int   g_rowptr[NN + 1];
__device__ int2  g_edge[EE];          // packed {src, __float_as_int(ea)}
__device__ float g_Q[NN * DD];
__device__ float g_KV[NN * 2 * DD];   // per node: [0:64)=K, [64:128)=V (one 512B row)
__device__ float g_S[NN * DD];        // skip = x @ Wskip + bskip
__device__ float g_h[NN * DD];        // layer output (ReLU already applied for l<L-1)
__device__ float g_pool[GG * DD];
__device__ int   g_cnt[GG];

// ---------------- packed fp32x2 FMA (sm_100+) ----------------
__device__ __forceinline__ float2 ffma2(float2 x, float2 w, float2 a) {
    float2 r;
    asm("fma.rn.f32x2 %0, %1, %2, %3;"
        : "=l"(reinterpret_cast<unsigned long long&>(r))
        : "l"(reinterpret_cast<unsigned long long&>(x)),
          "l"(reinterpret_cast<unsigned long long&>(w)),
          "l"(reinterpret_cast<unsigned long long&>(a)));
    return r;
}

// ---------------- utility ----------------
__global__ void zero_scratch_kernel() {
    int idx = blockIdx.x * blockDim.x + threadIdx.x;
    int stride = gridDim.x * blockDim.x;
    for (int i = idx; i < NN; i += stride) { g_deg[i] = 0; g_fill[i] = 0; }
    for (int i = idx; i < GG * DD; i += stride) g_pool[i] = 0.f;
    for (int i = idx; i < GG; i += stride) g_cnt[i] = 0;
}

// 4 edges per thread via int4 loads (EE % 4 == 0)
__global__ void hist_kernel(const int* __restrict__ dst) {
    int t = blockIdx.x * blockDim.x + threadIdx.x;
    int e = t * 4;
    if (e + 3 < EE) {
        int4 d4 = *reinterpret_cast<const int4*>(dst + e);
        atomicAdd(&g_deg[d4.x], 1);
        atomicAdd(&g_deg[d4.y], 1);
        atomicAdd(&g_deg[d4.z], 1);
        atomicAdd(&g_deg[d4.w], 1);
    } else {
        for (int i = e; i < EE; i++) atomicAdd(&g_deg[dst[i]], 1);
    }
}

// raking scan: 1024 threads, each owns 49 consecutive elements.
__global__ void scan_kernel() {
    __shared__ int sh[1024];
    int t = threadIdx.x;
    const int PER = (NN + 1023) / 1024;  // 49
    int base = t * PER;
    int sum = 0;
#pragma unroll 7
    for (int i = 0; i < PER; i++) {
        int idx = base + i;
        if (idx < NN) sum += g_deg[idx];
    }
    sh[t] = sum;
    __syncthreads();
    for (int off = 1; off < 1024; off <<= 1) {
        int v = (t >= off) ? sh[t - off] : 0;
        __syncthreads();
        sh[t] += v;
        __syncthreads();
    }
    int run = sh[t] - sum;  // exclusive prefix
    for (int i = 0; i < PER; i++) {
        int idx = base + i;
        if (idx < NN) {
            g_rowptr[idx] = run;
            run += g_deg[idx];
        }
    }
    if (t == 1023) g_rowptr[NN] = sh[1023];
}

__global__ void scatter_kernel(const int* __restrict__ src, const int* __restrict__ dst,
                               const float* __restrict__ ea) {
    int e = blockIdx.x * blockDim.x + threadIdx.x;
    if (e >= EE) return;
    int d = dst[e];
    int pos = g_rowptr[d] + atomicAdd(&g_fill[d], 1);
    g_edge[pos] = make_int2(src[e], __float_as_int(ea[e]));
}

// ---------------- fused QKV+Skip projection, FFMA2, TN=32 (proven config) --------
#define TN 32
__global__ __launch_bounds__(256) void gemm_qkvs(
    const float* __restrict__ X, int useX,
    const float* __restrict__ Wq, const float* __restrict__ bq,
    const float* __restrict__ Wk, const float* __restrict__ bk,
    const float* __restrict__ Wv, const float* __restrict__ bv,
    const float* __restrict__ Wsk, const float* __restrict__ bsk)
{
    extern __shared__ float sh[];
    float* Wsm = sh;                 // [64][256]
    float* Xsm = sh + 64 * 256;      // [TN][64]
    int tid = threadIdx.x;

    for (int i = tid; i < 64 * 64; i += 256) {
        int d = i >> 6, j = i & 63;
        Wsm[d * 256 + j]       = Wq[i];
        Wsm[d * 256 + 64 + j]  = Wk[i];
        Wsm[d * 256 + 128 + j] = Wv[i];
        Wsm[d * 256 + 192 + j] = Wsk[i];
    }
    int nodeBase = blockIdx.x * TN;
    for (int i = tid; i < TN * 64; i += 256) {
        int n = i >> 6, d = i & 63;
        int gn = nodeBase + n;
        float v = 0.f;
        if (gn < NN) v = useX ? X[gn * 64 + d] : g_h[gn * 64 + d];
        Xsm[n * 64 + d] = v;
    }
    __syncthreads();

    int cg = tid & 31;   // col pair base = 2*cg
    int ng = tid >> 5;   // nodes ng*4 + n
    float2 acc[4][4];
#pragma unroll
    for (int n = 0; n < 4; n++)
#pragma unroll
        for (int c = 0; c < 4; c++) acc[n][c] = make_float2(0.f, 0.f);

#pragma unroll 4
    for (int d = 0; d < 64; d++) {
        float2 w[4];
#pragma unroll
        for (int c = 0; c < 4; c++)
            w[c] = *reinterpret_cast<const float2*>(&Wsm[d * 256 + 2 * cg + 64 * c]);
#pragma unroll
        for (int n = 0; n < 4; n++) {
            float xv = Xsm[(ng * 4 + n) * 64 + d];
            float2 xx = make_float2(xv, xv);
#pragma unroll
            for (int c = 0; c < 4; c++) acc[n][c] = ffma2(xx, w[c], acc[n][c]);
        }
    }

    int colp = 2 * cg;
    float2 bQ = make_float2(bq[colp],  bq[colp + 1]);
    float2 bK = make_float2(bk[colp],  bk[colp + 1]);
    float2 bV = make_float2(bv[colp],  bv[colp + 1]);
    float2 bS = make_float2(bsk[colp], bsk[colp + 1]);
#pragma unroll
    for (int n = 0; n < 4; n++) {
        int gn = nodeBase + ng * 4 + n;
        if (gn >= NN) continue;
        float2 rq = make_float2(acc[n][0].x + bQ.x, acc[n][0].y + bQ.y);
        float2 rk = make_float2(acc[n][1].x + bK.x, acc[n][1].y + bK.y);
        float2 rv = make_float2(acc[n][2].x + bV.x, acc[n][2].y + bV.y);
        float2 rs = make_float2(acc[n][3].x + bS.x, acc[n][3].y + bS.y);
        *reinterpret_cast<float2*>(&g_Q[gn * 64 + colp])        = rq;
        *reinterpret_cast<float2*>(&g_KV[gn * 128 + colp])      = rk;
        *reinterpret_cast<float2*>(&g_KV[gn * 128 + 64 + colp]) = rv;
        *reinterpret_cast<float2*>(&g_S[gn * 64 + colp])        = rs;
    }
}

// ---------------- attention: HALF-WARP per node, float4 lanes, 64-thread blocks ----
__global__ __launch_bounds__(64) void attn_kernel(const float* __restrict__ We_l,
                                                  float* __restrict__ dout, int toDout)
{
    int gid = (blockIdx.x * blockDim.x + threadIdx.x) >> 4;   // node id
    int l16 = threadIdx.x & 15;
    if (gid >= NN) return;
    unsigned gmask = 0xFFFFu << (threadIdx.x & 16);           // this half-warp

    float4 q = reinterpret_cast<const float4*>(g_Q + (size_t)gid * 64)[l16];
    q.x *= 0.25f; q.y *= 0.25f; q.z *= 0.25f; q.w *= 0.25f;   // fold 1/sqrt(C)
    float4 we = reinterpret_cast<const float4*>(We_l)[l16];

    float lsum = 0.f;
    float4 acc = make_float4(0.f, 0.f, 0.f, 0.f);

    int beg = g_rowptr[gid], end = g_rowptr[gid + 1];
    int p = beg;

#define EDGE_BODY(K, V, EAI)                                              \
    {                                                                     \
        float ea = __int_as_float(EAI);                                   \
        float kx = fmaf(ea, we.x, (K).x);                                 \
        float ky = fmaf(ea, we.y, (K).y);                                 \
        float kz = fmaf(ea, we.z, (K).z);                                 \
        float kw = fmaf(ea, we.w, (K).w);                                 \
        float d = q.x * kx;                                               \
        d = fmaf(q.y, ky, d);                                             \
        d = fmaf(q.z, kz, d);                                             \
        d = fmaf(q.w, kw, d);                                             \
        d += __shfl_xor_sync(gmask, d, 1);                                \
        d += __shfl_xor_sync(gmask, d, 2);                                \
        float pe = __expf(d);                                             \
        acc.x = fmaf(pe, fmaf(ea, we.x, (V).x), acc.x);                   \
        acc.y = fmaf(pe, fmaf(ea, we.y, (V).y), acc.y);                   \
        acc.z = fmaf(pe, fmaf(ea, we.z, (V).z), acc.z);                   \
        acc.w = fmaf(pe, fmaf(ea, we.w, (V).w), acc.w);                   \
        lsum += pe;                                                       \
    }

    for (; p + 2 <= end; p += 2) {
        int2 ed0 = g_edge[p];
        int2 ed1 = g_edge[p + 1];
        const float4* kv0 = reinterpret_cast<const float4*>(g_KV + (size_t)ed0.x * 128);
        const float4* kv1 = reinterpret_cast<const float4*>(g_KV + (size_t)ed1.x * 128);
        float4 k0 = kv0[l16], v0 = kv0[16 + l16];
        float4 k1 = kv1[l16], v1 = kv1[16 + l16];
        EDGE_BODY(k0, v0, ed0.y)
        EDGE_BODY(k1, v1, ed1.y)
    }
    if (p < end) {
        int2 ed = g_edge[p];
        const float4* kvp = reinterpret_cast<const float4*>(g_KV + (size_t)ed.x * 128);
        float4 k = kvp[l16], v = kvp[16 + l16];
        EDGE_BODY(k, v, ed.y)
    }
#undef EDGE_BODY

    float inv = (lsum > 0.f) ? 1.f / lsum : 0.f;
    float4 s = reinterpret_cast<const float4*>(g_S + (size_t)gid * 64)[l16];
    float4 r;
    r.x = fmaf(acc.x, inv, s.x);
    r.y = fmaf(acc.y, inv, s.y);
    r.z = fmaf(acc.z, inv, s.z);
    r.w = fmaf(acc.w, inv, s.w);
    if (toDout) {
        reinterpret_cast<float4*>(dout + (size_t)gid * 64)[l16] = r;
    } else {
        r.x = fmaxf(r.x, 0.f); r.y = fmaxf(r.y, 0.f);
        r.z = fmaxf(r.z, 0.f); r.w = fmaxf(r.w, 0.f);
        reinterpret_cast<float4*>(g_h + (size_t)gid * 64)[l16] = r;
    }
}

// ---------------- pooling: batch sorted -> run-length accumulate (+count) ----------------
__global__ void pool_kernel(const float* __restrict__ h, const int* __restrict__ batch) {
    int c = threadIdx.x;           // 64 threads = channels
    int n0 = blockIdx.x * 32;
    int cur = -1;
    float acc = 0.f;
    int cnt = 0;
    for (int i = 0; i < 32; i++) {
        int n = n0 + i;
        if (n >= NN) break;
        int b = batch[n];
        if (b != cur) {
            if (cur >= 0) {
                atomicAdd(&g_pool[cur * 64 + c], acc);
                if (c == 0) atomicAdd(&g_cnt[cur], cnt);
            }
            cur = b; acc = 0.f; cnt = 0;
        }
        acc += h[n * 64 + c];
        cnt++;
    }
    if (cur >= 0) {
        atomicAdd(&g_pool[cur * 64 + c], acc);
        if (c == 0) atomicAdd(&g_cnt[cur], cnt);
    }
}

// ---------------- graph MLP head ----------------
__global__ void mlp_kernel(const float* __restrict__ W1, const float* __restrict__ b1,
                           const float* __restrict__ W2, const float* __restrict__ b2,
                           const float* __restrict__ W3, const float* __restrict__ b3,
                           float* __restrict__ out)
{
    int g = blockIdx.x;
    int t = threadIdx.x; // 128
    __shared__ float gsh[64], h1[64], h2[16];
    if (t < 64) {
        float c = fmaxf((float)g_cnt[g], 1.f);
        gsh[t] = g_pool[g * 64 + t] / c;
    }
    __syncthreads();
    if (t < 64) {
        float a = b1[t];
#pragma unroll 8
        for (int d = 0; d < 64; d++) a = fmaf(gsh[d], W1[d * 64 + t], a);
        h1[t] = fmaxf(a, 0.f);
    }
    __syncthreads();
    if (t < 16) {
        float a = b2[t];
#pragma unroll 8
        for (int d = 0; d < 64; d++) a = fmaf(h1[d], W2[d * 16 + t], a);
        h2[t] = fmaxf(a, 0.f);
    }
    __syncthreads();
    {
        float a = b3[t];
#pragma unroll
        for (int d = 0; d < 16; d++) a = fmaf(h2[d], W3[d * 128 + t], a);
        out[g * 128 + t] = a;
    }
}

// ---------------- launch (serial, R11-proven ordering) ----------------
extern "C" void kernel_launch(void* const* d_in, const int* in_sizes, int n_in,
                              void* d_out, int out_size)
{
    // Resolve input ordering by size probe (edge_index has 2*E elements).
    const int* ei;
    const int* batch;
    int iW;
    if (in_sizes[2] == 2 * EE) {          // dict order: x, ea, edge_index, batch, Wq...
        ei    = (const int*)d_in[2];
        batch = (const int*)d_in[3];
        iW = 4;
    } else {                               // signature order: x, ea, Wq..., edge_index, batch
        ei    = (const int*)d_in[17];
        batch = (const int*)d_in[18];
        iW = 2;
    }
    const float* x    = (const float*)d_in[0];
    const float* ea   = (const float*)d_in[1];
    const float* Wq   = (const float*)d_in[iW + 0];
    const float* bq   = (const float*)d_in[iW + 1];
    const float* Wk   = (const float*)d_in[iW + 2];
    const float* bk   = (const float*)d_in[iW + 3];
    const float* Wv   = (const float*)d_in[iW + 4];
    const float* bv   = (const float*)d_in[iW + 5];
    const float* We   = (const float*)d_in[iW + 6];
    const float* Wsk  = (const float*)d_in[iW + 7];
    const float* bsk  = (const float*)d_in[iW + 8];
    const float* W1   = (const float*)d_in[iW + 9];
    const float* b1   = (const float*)d_in[iW + 10];
    const float* W2   = (const float*)d_in[iW + 11];
    const float* b2   = (const float*)d_in[iW + 12];
    const float* W3   = (const float*)d_in[iW + 13];
    const float* b3   = (const float*)d_in[iW + 14];

    const int* srcIdx = ei;
    const int* dstIdx = ei + EE;
    float* out = (float*)d_out;

    static bool attr_set = false;
    if (!attr_set) {
        cudaFuncSetAttribute(gemm_qkvs, cudaFuncAttributeMaxDynamicSharedMemorySize,
                             (64 * 256 + TN * 64) * sizeof(float));
        attr_set = true;
    }

    // CSR build (serial; reused by all 3 layers)
    zero_scratch_kernel<<<256, 256>>>();
    hist_kernel<<<(EE / 4 + 255) / 256, 256>>>(dstIdx);
    scan_kernel<<<1, 1024>>>();
    scatter_kernel<<<(EE + 255) / 256, 256>>>(srcIdx, dstIdx, ea);

    size_t smem = (64 * 256 + TN * 64) * sizeof(float);
    int gemmGrid = (NN + TN - 1) / TN;
    int attnGrid = (NN * 16 + 63) / 64;

    for (int l = 0; l < LLAYERS; l++) {
        int useX = (l == 0) ? 1 : 0;
        gemm_qkvs<<<gemmGrid, 256, smem>>>(
            x, useX,
            Wq + l * DD * DD, bq + l * DD,
            Wk + l * DD * DD, bk + l * DD,
            Wv + l * DD * DD, bv + l * DD,
            Wsk + l * DD * DD, bsk + l * DD);
        int toDout = (l == LLAYERS - 1) ? 1 : 0;
        attn_kernel<<<attnGrid, 64>>>(We + l * DD, out, toDout);
    }

    // pool over final node embeddings (already in d_out) + MLP head
    pool_kernel<<<(NN + 31) / 32, 64>>>(out, batch);
    mlp_kernel<<<GG, 128>>>(W1, b1, W2, b2, W3, b3, out + (size_t)NN * DD);
}